// round 9
// baseline (speedup 1.0000x reference)
#include <cuda_runtime.h>

#define NHEADS 4
typedef unsigned long long u64;

// Scratch (allocation-free). Zero at module load; epilogue re-zeroes after
// reading so every graph replay observes zeros (deterministic).
__device__ float g_S[NHEADS][64];          // sum_n w[h,n] * u_n
__device__ float g_z[NHEADS];              // sum_n w[h,n]
__device__ unsigned int g_ctr;             // last-block-done counter

__device__ __forceinline__ float tanh_fast(float x) {
    float y; asm("tanh.approx.f32 %0, %1;" : "=f"(y) : "f"(x)); return y;
}
__device__ __forceinline__ float exp2_fast(float x) {
    float y; asm("ex2.approx.f32 %0, %1;" : "=f"(y) : "f"(x)); return y;
}
// ---- packed f32x2 helpers (used only in the accumulation stage) ----
__device__ __forceinline__ u64 pack2(float lo, float hi) {
    u64 r; asm("mov.b64 %0, {%1, %2};" : "=l"(r) : "f"(lo), "f"(hi)); return r;
}
__device__ __forceinline__ u64 fma2(u64 a, u64 b, u64 c) {
    u64 d; asm("fma.rn.f32x2 %0, %1, %2, %3;" : "=l"(d) : "l"(a), "l"(b), "l"(c)); return d;
}
__device__ __forceinline__ void unpack2(u64 v, float& lo, float& hi) {
    asm("mov.b64 {%0, %1}, %2;" : "=f"(lo), "=f"(hi) : "l"(v));
}

// ---------------------------------------------------------------------------
// Single fused kernel, tuned for occupancy (3 CTAs/SM).
// Prologue (per block): atil[h][j] = (scale*log2e) * (W2^T Wk_h^T q_h)[j].
// Main loop: warp cooperates; lane l owns hidden dims j0=l, j1=l+32.
//   8 points/round. Scores for value pairs (i, i+16) are generated and the
//   m=16 butterfly stage is fused immediately (keeps only p[16] live);
//   stages 8..1 finish the 32 warp-sums; score(pt,h) lands at lane 4*pt+h.
//   exp2 weights broadcast via smem LDS.128; accumulation packed f32x2.
// Epilogue: last finished block computes hbar/pooled/out, re-zeroes scratch.
//   RACE FIX (R8->R9): __threadfence by ALL threads + __syncthreads BEFORE
//   the g_ctr increment, so a block is only counted done after every one of
//   its warps has made its g_S/g_z atomics visible.
// ---------------------------------------------------------------------------
__global__ void __launch_bounds__(256, 3)
main_kernel(const float* __restrict__ rr,
            const float* __restrict__ ri,
            const float* __restrict__ W1,
            const float* __restrict__ b1,
            const float* __restrict__ W2,
            const float* __restrict__ query,
            const float* __restrict__ ipw,
            const float* __restrict__ ipb,
            const float* __restrict__ b2,
            const float* __restrict__ opw,
            const float* __restrict__ opb,
            float* __restrict__ out,
            int N) {
    __shared__ float qsh[64];
    __shared__ float ash[NHEADS][64];     // reused as hbar in epilogue
    __shared__ float atil[NHEADS][64];
    __shared__ float wb[8][2][32];        // per-warp double-buffered weights
    __shared__ float invz[NHEADS];
    __shared__ bool  isLast;

    const int t    = threadIdx.x;
    const int lane = t & 31;
    const int wid  = t >> 5;

    // ---- prologue: q = query @ Wq^T + bq (4 threads per output) ----
    {
        int o = t >> 2, part = t & 3;
        float s = 0.f;
        const float* row = ipw + o * 64 + part * 16;
        const float* qp  = query + part * 16;
        #pragma unroll
        for (int i = 0; i < 16; ++i) s = fmaf(qp[i], row[i], s);
        s += __shfl_xor_sync(0xffffffffu, s, 1);
        s += __shfl_xor_sync(0xffffffffu, s, 2);
        if (part == 0) qsh[o] = s + ipb[o];
    }
    __syncthreads();
    // ---- a_h[c] = sum_d q[16h+d] * Wk[16h+d, c]  (Wk = ipw rows [64,128)) ----
    {
        int h = t >> 6, c = t & 63;
        float a = 0.f;
        #pragma unroll 4
        for (int d = 0; d < 16; ++d)
            a = fmaf(qsh[16 * h + d], ipw[(64 + 16 * h + d) * 64 + c], a);
        ash[h][c] = a;
    }
    __syncthreads();
    // ---- atil_h[c] = (0.25*log2e) * sum_m a_h[m] * W2[m,c] ----
    {
        const float SC = 0.25f * 1.4426950408889634f;  // scale * log2(e)
        int h = t >> 6, c = t & 63;
        float s = 0.f;
        #pragma unroll 8
        for (int m = 0; m < 64; ++m) s = fmaf(ash[h][m], W2[m * 64 + c], s);
        atil[h][c] = s * SC;
    }
    __syncthreads();

    // ---- per-lane constants (SiLU's 0.5 folded into W1/b1) ----
    const int j0 = lane, j1 = lane + 32;
    const float ka0 = 0.5f * W1[2 * j0], kb0 = 0.5f * W1[2 * j0 + 1], kc0 = 0.5f * b1[j0];
    const float ka1 = 0.5f * W1[2 * j1], kb1 = 0.5f * W1[2 * j1 + 1], kc1 = 0.5f * b1[j1];
    float A0[NHEADS], A1[NHEADS];
    #pragma unroll
    for (int h = 0; h < NHEADS; ++h) { A0[h] = atil[h][j0]; A1[h] = atil[h][j1]; }

    // Packed accumulators: (head pair) x (dim j0/j1)
    u64 acc0_01 = 0, acc0_23 = 0, acc1_01 = 0, acc1_23 = 0;
    float zloc = 0.f;   // lane-local sum of this lane's own em values

    const int gwarp  = (blockIdx.x * blockDim.x + t) >> 5;
    const int nwarps = (gridDim.x * blockDim.x) >> 5;
    const int G = N >> 3;
    const int chunk = (G + nwarps - 1) / nwarps;
    const int gs = gwarp * chunk;
    const int ge = min(G, gs + chunk);

    const float4* rr4 = (const float4*)rr;
    const float4* ri4 = (const float4*)ri;
    const bool hi16 = (lane & 16) != 0;

    for (int g = gs; g < ge; ++g) {
        float4 ra = __ldg(rr4 + 2 * g), rb = __ldg(rr4 + 2 * g + 1);
        float4 ia = __ldg(ri4 + 2 * g), ib = __ldg(ri4 + 2 * g + 1);
        float re[8] = {ra.x, ra.y, ra.z, ra.w, rb.x, rb.y, rb.z, rb.w};
        float im[8] = {ia.x, ia.y, ia.z, ia.w, ib.x, ib.y, ib.z, ib.w};
        float u0[8], u1[8];
        #pragma unroll
        for (int pt = 0; pt < 8; ++pt) {
            float h0 = fmaf(ka0, re[pt], fmaf(kb0, im[pt], kc0));   // t/2
            float h1 = fmaf(ka1, re[pt], fmaf(kb1, im[pt], kc1));
            u0[pt] = fmaf(h0, tanh_fast(h0), h0);                   // silu
            u1[pt] = fmaf(h1, tanh_fast(h1), h1);
        }
        // Score generation with fused m=16 stage: value i = score(pt=i>>2,h=i&3),
        // partner value i+16 is the same head for pt+4. Only p[16] stays live.
        float p[16];
        #pragma unroll
        for (int pt = 0; pt < 4; ++pt) {
            #pragma unroll
            for (int h = 0; h < NHEADS; ++h) {
                float sLo = fmaf(A0[h], u0[pt],     A1[h] * u1[pt]);
                float sHi = fmaf(A0[h], u0[pt + 4], A1[h] * u1[pt + 4]);
                float keep = hi16 ? sHi : sLo;
                float send = hi16 ? sLo : sHi;
                p[pt * 4 + h] = keep + __shfl_xor_sync(0xffffffffu, send, 16);
            }
        }
        // Remaining butterfly stages: 15 shfls; lane l ends with warp-sum of
        // score(pt=l>>2, h=l&3) in p[0].
        #pragma unroll
        for (int m = 8; m >= 1; m >>= 1) {
            const bool hi = (lane & m) != 0;
            #pragma unroll
            for (int i = 0; i < m; ++i) {
                float keep = hi ? p[i + m] : p[i];
                float send = hi ? p[i] : p[i + m];
                p[i] = keep + __shfl_xor_sync(0xffffffffu, send, m);
            }
        }
        float em = exp2_fast(p[0]);   // exp(score(pt=lane>>2, h=lane&3))
        zloc += em;
        // Broadcast the 32 weights through smem (double-buffered per warp).
        wb[wid][g & 1][lane] = em;
        __syncwarp();
        const float4* wp = (const float4*)&wb[wid][g & 1][0];
        #pragma unroll
        for (int pt = 0; pt < 8; ++pt) {
            float4 w4 = wp[pt];                      // weights h=0..3 for pt
            u64 W01 = pack2(w4.x, w4.y), W23 = pack2(w4.z, w4.w);
            u64 D0 = pack2(u0[pt], u0[pt]), D1 = pack2(u1[pt], u1[pt]);
            acc0_01 = fma2(W01, D0, acc0_01);
            acc0_23 = fma2(W23, D0, acc0_23);
            acc1_01 = fma2(W01, D1, acc1_01);
            acc1_23 = fma2(W23, D1, acc1_23);
        }
    }

    float acc0[NHEADS], acc1[NHEADS];
    unpack2(acc0_01, acc0[0], acc0[1]); unpack2(acc0_23, acc0[2], acc0[3]);
    unpack2(acc1_01, acc1[0], acc1[1]); unpack2(acc1_23, acc1[2], acc1[3]);

    // Tail points (N % 8): warp 0 only, scalar path.
    float ztl[NHEADS] = {0.f, 0.f, 0.f, 0.f};
    if (gwarp == 0) {
        for (int n = (G << 3); n < N; ++n) {
            float re = rr[n], im = ri[n];
            float h0 = fmaf(ka0, re, fmaf(kb0, im, kc0));
            float h1 = fmaf(ka1, re, fmaf(kb1, im, kc1));
            float v0 = fmaf(h0, tanh_fast(h0), h0);
            float v1 = fmaf(h1, tanh_fast(h1), h1);
            #pragma unroll
            for (int h = 0; h < NHEADS; ++h) {
                float s = fmaf(A0[h], v0, A1[h] * v1);
                #pragma unroll
                for (int m = 16; m >= 1; m >>= 1)
                    s += __shfl_xor_sync(0xffffffffu, s, m);
                float w = exp2_fast(s);
                ztl[h] += w;
                acc0[h] = fmaf(w, v0, acc0[h]);
                acc1[h] = fmaf(w, v1, acc1[h]);
            }
        }
    }

    // Commit warp partials (lane-distinct addresses; no intra-warp contention)
    #pragma unroll
    for (int h = 0; h < NHEADS; ++h) {
        atomicAdd(&g_S[h][j0], acc0[h]);
        atomicAdd(&g_S[h][j1], acc1[h]);
    }
    // zloc at lane l belongs to head h=l&3; same-h lanes differ in bits {2,3,4}
    float zs = zloc + __shfl_xor_sync(0xffffffffu, zloc, 16);
    zs += __shfl_xor_sync(0xffffffffu, zs, 8);
    zs += __shfl_xor_sync(0xffffffffu, zs, 4);
    if (lane < NHEADS) atomicAdd(&g_z[lane], zs);
    if (gwarp == 0 && lane == 0) {
        #pragma unroll
        for (int h = 0; h < NHEADS; ++h) atomicAdd(&g_z[h], ztl[h]);
    }

    // ---- epilogue: last block computes the output -------------------------
    // RACE FIX: every thread fences its own atomics, then the block barrier
    // guarantees ALL warps of this block have fenced before thread 0 counts
    // the block as done. Only then can the epilogue's g_S reads be complete.
    __threadfence();
    __syncthreads();
    if (t == 0) {
        unsigned v = atomicAdd(&g_ctr, 1u);
        isLast = (v == gridDim.x - 1);
        if (isLast) g_ctr = 0;           // all blocks incremented; safe reset
    }
    __syncthreads();
    if (!isLast) return;

    float* hbar = &ash[0][0];            // reuse [4][64]
    float* pooled = qsh;                 // reuse [64]
    if (t < NHEADS) invz[t] = __frcp_rn(__ldcg(&g_z[t]));
    __syncthreads();
    {
        int h = t >> 6, j = t & 63;
        float s = 0.f;
        #pragma unroll 8
        for (int m = 0; m < 64; ++m)
            s = fmaf(W2[j * 64 + m], __ldcg(&g_S[h][m]), s);
        hbar[h * 64 + j] = fmaf(s, invz[h], b2[j]);
    }
    __syncthreads();
    // scratch reset for next graph replay (all reads of g_S/g_z done)
    ((float*)g_S)[t] = 0.f;
    if (t < NHEADS) g_z[t] = 0.f;
    if (t < 64) {
        int h = t >> 4;
        float s = ipb[128 + t];          // Wv row (128+t) dot hbar_h + bv
        #pragma unroll 8
        for (int m = 0; m < 64; ++m)
            s = fmaf(ipw[(128 + t) * 64 + m], hbar[h * 64 + m], s);
        pooled[t] = s;
    }
    __syncthreads();
    if (t < 64) {
        float s = opb[t];
        #pragma unroll 8
        for (int k = 0; k < 64; ++k) s = fmaf(opw[t * 64 + k], pooled[k], s);
        out[t] = s;
    }
}

// ---------------------------------------------------------------------------
extern "C" void kernel_launch(void* const* d_in, const int* in_sizes, int n_in,
                              void* d_out, int out_size) {
    // Inputs (metadata order): rho_real, rho_imag, l_A, l_B, [Z_A, Z_B,]
    // W1, b1, W2, b2, query, in_proj_w, in_proj_b, out_proj_w, out_proj_b.
    const float* rr    = (const float*)d_in[0];
    const float* ri    = (const float*)d_in[1];
    const float* W1    = (const float*)d_in[n_in - 9];
    const float* b1    = (const float*)d_in[n_in - 8];
    const float* W2    = (const float*)d_in[n_in - 7];
    const float* b2    = (const float*)d_in[n_in - 6];
    const float* query = (const float*)d_in[n_in - 5];
    const float* ipw   = (const float*)d_in[n_in - 4];
    const float* ipb   = (const float*)d_in[n_in - 3];
    const float* opw   = (const float*)d_in[n_in - 2];
    const float* opb   = (const float*)d_in[n_in - 1];
    int N = in_sizes[0];

    main_kernel<<<444, 256>>>(rr, ri, W1, b1, W2, query, ipw, ipb,
                              b2, opw, opb, (float*)d_out, N);
}